// round 3
// baseline (speedup 1.0000x reference)
#include <cuda_runtime.h>

#define B_SZ 1024
#define C_SZ 128
#define ELL 16
#define EQ 3
#define E_SZ 10
#define P3 23
#define P2 5
#define NR 768           // EQ*ELL*ELL rows (w,xx,v)
#define D3_PER_EC 12288  // NR*ELL
#define OUT_STRIDE 384   // C_SZ*EQ

// Scratch: D3[e][c][i][r] with r innermost for coalesced loads in kernel C.
__device__ float g_D3[E_SZ * C_SZ * D3_PER_EC];
__device__ int g_order[B_SZ];
__device__ int g_bstart[E_SZ + 1];

// ---------------------------------------------------------------------------
// Kernel A: bucket batch indices by element (y is exact one-hot).
// Order within a bucket is atomic-nondeterministic, but each b's output is
// computed identically regardless of order -> deterministic results.
// ---------------------------------------------------------------------------
__global__ void bucket_kernel(const float* __restrict__ y) {
    __shared__ int cnt[E_SZ];
    __shared__ int pfx[E_SZ + 1];
    int b = threadIdx.x;
    if (b < E_SZ) cnt[b] = 0;
    __syncthreads();
    int e = 0;
#pragma unroll
    for (int j = 1; j < E_SZ; j++)
        if (y[b * E_SZ + j] > 0.5f) e = j;
    int idx = atomicAdd(&cnt[e], 1);
    __syncthreads();
    if (b == 0) {
        int s = 0;
        for (int j = 0; j < E_SZ; j++) { pfx[j] = s; s += cnt[j]; }
        pfx[E_SZ] = s;
    }
    __syncthreads();
    g_order[pfx[e] + idx] = b;
    if (b <= E_SZ) g_bstart[b] = pfx[b];
}

// ---------------------------------------------------------------------------
// Kernel B: D3[e,c,r,i] = sum_k U3[r,i,k] * w_max[e,k,c]
// Stored as g_D3[((e*C + c)*ELL + i)*NR + r].
// Grid (48, E), block 256. Each thread owns one (i,r), loops over c.
// ---------------------------------------------------------------------------
__global__ void __launch_bounds__(256) precomp_kernel(const float* __restrict__ U3,
                                                      const float* __restrict__ wmax) {
    int e = blockIdx.y;
    int o = blockIdx.x * 256 + threadIdx.x;  // 0..12287, o = i*NR + r
    int i = o / NR;
    int r = o % NR;

    __shared__ float ws[P3][C_SZ];
    for (int idx = threadIdx.x; idx < P3 * C_SZ; idx += 256)
        ws[idx / C_SZ][idx % C_SZ] = wmax[e * P3 * C_SZ + idx];
    __syncthreads();

    float u[P3];
    const float* up = U3 + (r * ELL + i) * P3;
#pragma unroll
    for (int k = 0; k < P3; k++) u[k] = up[k];

    float* ob = g_D3 + (size_t)e * C_SZ * D3_PER_EC + i * NR + r;
    for (int c0 = 0; c0 < C_SZ; c0 += 8) {
        float acc[8];
#pragma unroll
        for (int cc = 0; cc < 8; cc++) acc[cc] = 0.f;
#pragma unroll
        for (int k = 0; k < P3; k++) {
            float4 a = *(const float4*)&ws[k][c0];
            float4 bq = *(const float4*)&ws[k][c0 + 4];
            acc[0] += u[k] * a.x;  acc[1] += u[k] * a.y;
            acc[2] += u[k] * a.z;  acc[3] += u[k] * a.w;
            acc[4] += u[k] * bq.x; acc[5] += u[k] * bq.y;
            acc[6] += u[k] * bq.z; acc[7] += u[k] * bq.w;
        }
#pragma unroll
        for (int cc = 0; cc < 8; cc++)
            ob[(size_t)(c0 + cc) * D3_PER_EC] = acc[cc];
    }
}

// ---------------------------------------------------------------------------
// Kernel C: per (e,c) CTA; D3 slice cached in registers (48 f32/thread).
// Thread t <-> (xx = t>>4, v = t&15), w = 0..2.
// out[b,w] = sum over 256 threads of x_xx*x_v*(D2 + dot(D3_row, x))
//            + (v==0 threads) x_xx*D1[w,xx]
// ---------------------------------------------------------------------------
__global__ void __launch_bounds__(256) contract_kernel(
    const float* __restrict__ x, const float* __restrict__ U2,
    const float* __restrict__ U1, const float* __restrict__ w2,
    const float* __restrict__ w1, float* __restrict__ out) {
    int c = blockIdx.x, e = blockIdx.y;
    int t = threadIdx.x;
    int v = t & 15, xxi = t >> 4;
    int warp = t >> 5, lane = t & 31;

    // Load D3 rows into registers (fully coalesced: consecutive t -> consecutive addr)
    float d3[3][16];
    const float* base = g_D3 + (size_t)(e * C_SZ + c) * D3_PER_EC;
#pragma unroll
    for (int j = 0; j < 3; j++)
#pragma unroll
        for (int i = 0; i < 16; i++)
            d3[j][i] = base[i * NR + j * 256 + t];

    // D2[w,xx,v] = sum_k U2[r,k] * w2[e,k,c]  (r = j*256 + t)
    float d2[3];
#pragma unroll
    for (int j = 0; j < 3; j++) {
        float acc = 0.f;
#pragma unroll
        for (int k = 0; k < P2; k++)
            acc += U2[(j * 256 + t) * P2 + k] * w2[(e * P2 + k) * C_SZ + c];
        d2[j] = acc;
    }
    // D1[w,xx] = U1[w,xx,0] * w1[e,0,c]  (used only by v==0 threads)
    float w1v = w1[e * C_SZ + c];
    float d1[3];
#pragma unroll
    for (int j = 0; j < 3; j++) d1[j] = U1[j * ELL + xxi] * w1v;

    __shared__ float xs[16][16];        // b-tile of x vectors
    __shared__ int   border[16];        // gathered batch indices for this tile
    __shared__ float wpart[8][16][3];   // per-warp partials [warp][slot][w]

    int b0 = g_bstart[e], b1 = g_bstart[e + 1];
    for (int tb = b0; tb < b1; tb += 16) {
        int nb = min(16, b1 - tb);
        {
            int slot = t >> 4, ii = t & 15;
            if (slot < nb) {
                int bidx = g_order[tb + slot];
                if (ii == 0) border[slot] = bidx;
                xs[slot][ii] = x[((size_t)bidx * C_SZ + c) * ELL + ii];
            }
        }
        __syncthreads();

        for (int s = 0; s < nb; s++) {
            const float4* xq = (const float4*)xs[s];
            float4 q0 = xq[0], q1 = xq[1], q2 = xq[2], q3 = xq[3];
            float xvv = xs[s][v];
            float xxx = xs[s][xxi];
            float xvx = xvv * xxx;

            float contrib[3];
#pragma unroll
            for (int j = 0; j < 3; j++) {
                float acc = d2[j];
                acc += d3[j][0] * q0.x;  acc += d3[j][1] * q0.y;
                acc += d3[j][2] * q0.z;  acc += d3[j][3] * q0.w;
                acc += d3[j][4] * q1.x;  acc += d3[j][5] * q1.y;
                acc += d3[j][6] * q1.z;  acc += d3[j][7] * q1.w;
                acc += d3[j][8] * q2.x;  acc += d3[j][9] * q2.y;
                acc += d3[j][10] * q2.z; acc += d3[j][11] * q2.w;
                acc += d3[j][12] * q3.x; acc += d3[j][13] * q3.y;
                acc += d3[j][14] * q3.z; acc += d3[j][15] * q3.w;
                float cj = xvx * acc;
                if (v == 0) cj += xxx * d1[j];
                contrib[j] = cj;
            }
            // full 32-lane butterfly reduce, 3 values
#pragma unroll
            for (int off = 16; off > 0; off >>= 1) {
                contrib[0] += __shfl_xor_sync(0xffffffffu, contrib[0], off);
                contrib[1] += __shfl_xor_sync(0xffffffffu, contrib[1], off);
                contrib[2] += __shfl_xor_sync(0xffffffffu, contrib[2], off);
            }
            if (lane == 0) {
                wpart[warp][s][0] = contrib[0];
                wpart[warp][s][1] = contrib[1];
                wpart[warp][s][2] = contrib[2];
            }
        }
        __syncthreads();

        if (t < nb * 3) {
            int sl = t / 3, j = t - sl * 3;
            float sum = 0.f;
#pragma unroll
            for (int w8 = 0; w8 < 8; w8++) sum += wpart[w8][sl][j];
            out[(size_t)border[sl] * OUT_STRIDE + c * EQ + j] = sum;
        }
        __syncthreads();
    }
}

// ---------------------------------------------------------------------------
extern "C" void kernel_launch(void* const* d_in, const int* in_sizes, int n_in,
                              void* d_out, int out_size) {
    const float* x    = (const float*)d_in[0];
    const float* y    = (const float*)d_in[1];
    const float* U3   = (const float*)d_in[2];
    const float* U2   = (const float*)d_in[3];
    const float* U1   = (const float*)d_in[4];
    const float* wmax = (const float*)d_in[5];
    const float* w2   = (const float*)d_in[6];
    const float* w1   = (const float*)d_in[7];
    float* out = (float*)d_out;

    bucket_kernel<<<1, B_SZ>>>(y);
    precomp_kernel<<<dim3(48, E_SZ), 256>>>(U3, wmax);
    contract_kernel<<<dim3(C_SZ, E_SZ), 256>>>(x, U2, U1, w2, w1, out);
}

// round 6
// speedup vs baseline: 1.1207x; 1.1207x over previous
#include <cuda_runtime.h>

#define B_SZ 1024
#define C_SZ 128
#define ELL 16
#define EQ 3
#define E_SZ 10
#define P3 23
#define P2 5
#define NR 768           // EQ*ELL*ELL rows (w,xx,v)
#define D3_PER_EC 12288  // NR*ELL
#define OUT_STRIDE 384   // C_SZ*EQ

// Scratch: D3[e][c][r][i]  (i innermost -> per-thread LDG.128 pair loads)
__device__ float g_D3[E_SZ * C_SZ * D3_PER_EC];
__device__ int g_order[B_SZ];
__device__ int g_bstart[E_SZ + 1];

// ---- packed f32x2 helpers ----
static __device__ __forceinline__ unsigned long long pack2(float lo, float hi) {
    unsigned long long r;
    asm("mov.b64 %0, {%1, %2};" : "=l"(r) : "f"(lo), "f"(hi));
    return r;
}
static __device__ __forceinline__ void unpack2(float& lo, float& hi, unsigned long long v) {
    asm("mov.b64 {%0, %1}, %2;" : "=f"(lo), "=f"(hi) : "l"(v));
}
static __device__ __forceinline__ unsigned long long fma2(unsigned long long a,
                                                          unsigned long long b,
                                                          unsigned long long c) {
    unsigned long long d;
    asm("fma.rn.f32x2 %0, %1, %2, %3;" : "=l"(d) : "l"(a), "l"(b), "l"(c));
    return d;
}

// ---------------------------------------------------------------------------
// Kernel A: bucket batch indices by element (y is exact one-hot).
// ---------------------------------------------------------------------------
__global__ void bucket_kernel(const float* __restrict__ y) {
    __shared__ int cnt[E_SZ];
    __shared__ int pfx[E_SZ + 1];
    int b = threadIdx.x;
    if (b < E_SZ) cnt[b] = 0;
    __syncthreads();
    int e = 0;
#pragma unroll
    for (int j = 1; j < E_SZ; j++)
        if (y[b * E_SZ + j] > 0.5f) e = j;
    int idx = atomicAdd(&cnt[e], 1);
    __syncthreads();
    if (b == 0) {
        int s = 0;
        for (int j = 0; j < E_SZ; j++) { pfx[j] = s; s += cnt[j]; }
        pfx[E_SZ] = s;
    }
    __syncthreads();
    g_order[pfx[e] + idx] = b;
    if (b <= E_SZ) g_bstart[b] = pfx[b];
}

// ---------------------------------------------------------------------------
// Kernel B: D3[e,c,r,i] = sum_k U3[r,i,k] * w_max[e,k,c]
// Stored as g_D3[(e*C + c)*D3_PER_EC + r*ELL + i]  (o = r*16+i per thread).
// ---------------------------------------------------------------------------
__global__ void __launch_bounds__(256) precomp_kernel(const float* __restrict__ U3,
                                                      const float* __restrict__ wmax) {
    int e = blockIdx.y;
    int o = blockIdx.x * 256 + threadIdx.x;  // 0..12287 = r*16 + i

    __shared__ float ws[P3][C_SZ];
    for (int idx = threadIdx.x; idx < P3 * C_SZ; idx += 256)
        ws[idx / C_SZ][idx % C_SZ] = wmax[e * P3 * C_SZ + idx];
    __syncthreads();

    float u[P3];
    const float* up = U3 + (size_t)o * P3;   // (r*ELL+i)*P3 == o*P3
#pragma unroll
    for (int k = 0; k < P3; k++) u[k] = up[k];

    float* ob = g_D3 + (size_t)e * C_SZ * D3_PER_EC + o;
    for (int c0 = 0; c0 < C_SZ; c0 += 8) {
        float acc[8];
#pragma unroll
        for (int cc = 0; cc < 8; cc++) acc[cc] = 0.f;
#pragma unroll
        for (int k = 0; k < P3; k++) {
            float4 a = *(const float4*)&ws[k][c0];
            float4 bq = *(const float4*)&ws[k][c0 + 4];
            acc[0] += u[k] * a.x;  acc[1] += u[k] * a.y;
            acc[2] += u[k] * a.z;  acc[3] += u[k] * a.w;
            acc[4] += u[k] * bq.x; acc[5] += u[k] * bq.y;
            acc[6] += u[k] * bq.z; acc[7] += u[k] * bq.w;
        }
#pragma unroll
        for (int cc = 0; cc < 8; cc++)
            ob[(size_t)(c0 + cc) * D3_PER_EC] = acc[cc];
    }
}

// ---------------------------------------------------------------------------
// Kernel C: per (e,c) CTA, 128 threads. Thread t owns xx = t>>3 and TWO v's
// (v0 = t&7, v1 = v0+8); w = 0..2. D3 rows live in registers as f32x2 i-pairs
// (96 regs). Inner dot products use fma.rn.f32x2 (2x fp32 FMA throughput).
// Butterfly reduce over 32 lanes (4 warps instead of 8 -> half the shuffles).
// ---------------------------------------------------------------------------
__global__ void __launch_bounds__(128) contract_kernel(
    const float* __restrict__ x, const float* __restrict__ U2,
    const float* __restrict__ U1, const float* __restrict__ w2,
    const float* __restrict__ w1, float* __restrict__ out) {
    int c = blockIdx.x, e = blockIdx.y;
    int t = threadIdx.x;
    int v0 = t & 7, xxi = t >> 3;
    int warp = t >> 5, lane = t & 31;

    const size_t ecoff = (size_t)(e * C_SZ + c) * D3_PER_EC;

    // d3p[h][j][q]: i-pairs of row r = j*256 + xxi*16 + v0 + 8*h
    unsigned long long d3p[2][3][8];
#pragma unroll
    for (int h = 0; h < 2; h++)
#pragma unroll
        for (int j = 0; j < 3; j++) {
            const ulonglong2* p = (const ulonglong2*)(g_D3 + ecoff +
                (size_t)(j * 256 + xxi * 16 + v0 + 8 * h) * ELL);
#pragma unroll
            for (int q = 0; q < 4; q++) {
                ulonglong2 u = p[q];
                d3p[h][j][2 * q] = u.x;
                d3p[h][j][2 * q + 1] = u.y;
            }
        }

    // d2 packed into lane0 of the accumulator start value
    unsigned long long d2p[2][3];
#pragma unroll
    for (int h = 0; h < 2; h++)
#pragma unroll
        for (int j = 0; j < 3; j++) {
            int r = j * 256 + xxi * 16 + v0 + 8 * h;
            float acc = 0.f;
#pragma unroll
            for (int k = 0; k < P2; k++)
                acc += U2[r * P2 + k] * w2[(e * P2 + k) * C_SZ + c];
            d2p[h][j] = pack2(acc, 0.f);
        }

    float w1v = w1[e * C_SZ + c];
    float d1[3];
#pragma unroll
    for (int j = 0; j < 3; j++) d1[j] = U1[j * ELL + xxi] * w1v;

    __shared__ __align__(16) float xs[16][16];  // b-tile of x vectors
    __shared__ int border[16];
    __shared__ float wpart[4][16][3];           // per-warp partials

    int b0 = g_bstart[e], b1 = g_bstart[e + 1];
    for (int tb = b0; tb < b1; tb += 16) {
        int nb = min(16, b1 - tb);
        {
            int slot = t >> 3, ii = (t & 7) * 2;  // 2 floats per thread
            if (slot < nb) {
                int bidx = g_order[tb + slot];
                if (ii == 0) border[slot] = bidx;
                float2 xv = *(const float2*)&x[((size_t)bidx * C_SZ + c) * ELL + ii];
                xs[slot][ii] = xv.x;
                xs[slot][ii + 1] = xv.y;
            }
        }
        __syncthreads();

        for (int s = 0; s < nb; s++) {
            const ulonglong2* xq = (const ulonglong2*)xs[s];
            unsigned long long xp[8];
#pragma unroll
            for (int q = 0; q < 4; q++) {
                ulonglong2 u = xq[q];
                xp[2 * q] = u.x;
                xp[2 * q + 1] = u.y;
            }
            float xxx = xs[s][xxi];
            float m0 = xs[s][v0] * xxx;
            float m1 = xs[s][v0 + 8] * xxx;

            float contrib[3];
#pragma unroll
            for (int j = 0; j < 3; j++) {
                unsigned long long a0 = d2p[0][j];
                unsigned long long a1 = d2p[1][j];
#pragma unroll
                for (int q = 0; q < 8; q++) {
                    a0 = fma2(d3p[0][j][q], xp[q], a0);
                    a1 = fma2(d3p[1][j][q], xp[q], a1);
                }
                float lo0, hi0, lo1, hi1;
                unpack2(lo0, hi0, a0);
                unpack2(lo1, hi1, a1);
                float cj = m0 * (lo0 + hi0) + m1 * (lo1 + hi1);
                if (v0 == 0) cj += xxx * d1[j];
                contrib[j] = cj;
            }
#pragma unroll
            for (int off = 16; off > 0; off >>= 1) {
                contrib[0] += __shfl_xor_sync(0xffffffffu, contrib[0], off);
                contrib[1] += __shfl_xor_sync(0xffffffffu, contrib[1], off);
                contrib[2] += __shfl_xor_sync(0xffffffffu, contrib[2], off);
            }
            if (lane == 0) {
                wpart[warp][s][0] = contrib[0];
                wpart[warp][s][1] = contrib[1];
                wpart[warp][s][2] = contrib[2];
            }
        }
        __syncthreads();

        if (t < nb * 3) {
            int sl = t / 3, j = t - sl * 3;
            float sum = wpart[0][sl][j] + wpart[1][sl][j] +
                        wpart[2][sl][j] + wpart[3][sl][j];
            out[(size_t)border[sl] * OUT_STRIDE + c * EQ + j] = sum;
        }
        __syncthreads();
    }
}

// ---------------------------------------------------------------------------
extern "C" void kernel_launch(void* const* d_in, const int* in_sizes, int n_in,
                              void* d_out, int out_size) {
    const float* x    = (const float*)d_in[0];
    const float* y    = (const float*)d_in[1];
    const float* U3   = (const float*)d_in[2];
    const float* U2   = (const float*)d_in[3];
    const float* U1   = (const float*)d_in[4];
    const float* wmax = (const float*)d_in[5];
    const float* w2   = (const float*)d_in[6];
    const float* w1   = (const float*)d_in[7];
    float* out = (float*)d_out;

    bucket_kernel<<<1, B_SZ>>>(y);
    precomp_kernel<<<dim3(48, E_SZ), 256>>>(U3, wmax);
    contract_kernel<<<dim3(C_SZ, E_SZ), 128>>>(x, U2, U1, w2, w1, out);
}

// round 7
// speedup vs baseline: 1.1606x; 1.0356x over previous
#include <cuda_runtime.h>

#define B_SZ 1024
#define C_SZ 128
#define ELL 16
#define EQ 3
#define E_SZ 10
#define P3 23
#define P2 5
#define NR 768           // EQ*ELL*ELL rows (w,xx,v)
#define D3_PER_EC 12288  // NR*ELL
#define OUT_STRIDE 384   // C_SZ*EQ
#define NCHUNK 2         // bucket split factor (grid.z)

// Scratch: D3[e][c][r][i]  (i innermost -> per-thread LDG.128 pair loads)
__device__ float g_D3[E_SZ * C_SZ * D3_PER_EC];
__device__ int g_order[B_SZ];
__device__ int g_bstart[E_SZ + 1];

// ---- packed f32x2 helpers ----
static __device__ __forceinline__ unsigned long long pack2(float lo, float hi) {
    unsigned long long r;
    asm("mov.b64 %0, {%1, %2};" : "=l"(r) : "f"(lo), "f"(hi));
    return r;
}
static __device__ __forceinline__ void unpack2(float& lo, float& hi, unsigned long long v) {
    asm("mov.b64 {%0, %1}, %2;" : "=f"(lo), "=f"(hi) : "l"(v));
}
static __device__ __forceinline__ unsigned long long fma2(unsigned long long a,
                                                          unsigned long long b,
                                                          unsigned long long c) {
    unsigned long long d;
    asm("fma.rn.f32x2 %0, %1, %2, %3;" : "=l"(d) : "l"(a), "l"(b), "l"(c));
    return d;
}

// ---------------------------------------------------------------------------
// Kernel A: bucket batch indices by element (y is exact one-hot).
// ---------------------------------------------------------------------------
__global__ void bucket_kernel(const float* __restrict__ y) {
    __shared__ int cnt[E_SZ];
    __shared__ int pfx[E_SZ + 1];
    int b = threadIdx.x;
    if (b < E_SZ) cnt[b] = 0;
    __syncthreads();
    int e = 0;
#pragma unroll
    for (int j = 1; j < E_SZ; j++)
        if (y[b * E_SZ + j] > 0.5f) e = j;
    int idx = atomicAdd(&cnt[e], 1);
    __syncthreads();
    if (b == 0) {
        int s = 0;
        for (int j = 0; j < E_SZ; j++) { pfx[j] = s; s += cnt[j]; }
        pfx[E_SZ] = s;
    }
    __syncthreads();
    g_order[pfx[e] + idx] = b;
    if (b <= E_SZ) g_bstart[b] = pfx[b];
}

// ---------------------------------------------------------------------------
// Kernel B: D3[e,c,r,i] = sum_k U3[r,i,k] * w_max[e,k,c]
// Stored as g_D3[(e*C + c)*D3_PER_EC + r*ELL + i].
// ---------------------------------------------------------------------------
__global__ void __launch_bounds__(256) precomp_kernel(const float* __restrict__ U3,
                                                      const float* __restrict__ wmax) {
    int e = blockIdx.y;
    int o = blockIdx.x * 256 + threadIdx.x;  // 0..12287 = r*16 + i

    __shared__ float ws[P3][C_SZ];
    for (int idx = threadIdx.x; idx < P3 * C_SZ; idx += 256)
        ws[idx / C_SZ][idx % C_SZ] = wmax[e * P3 * C_SZ + idx];
    __syncthreads();

    float u[P3];
    const float* up = U3 + (size_t)o * P3;
#pragma unroll
    for (int k = 0; k < P3; k++) u[k] = up[k];

    float* ob = g_D3 + (size_t)e * C_SZ * D3_PER_EC + o;
    for (int c0 = 0; c0 < C_SZ; c0 += 8) {
        float acc[8];
#pragma unroll
        for (int cc = 0; cc < 8; cc++) acc[cc] = 0.f;
#pragma unroll
        for (int k = 0; k < P3; k++) {
            float4 a = *(const float4*)&ws[k][c0];
            float4 bq = *(const float4*)&ws[k][c0 + 4];
            acc[0] += u[k] * a.x;  acc[1] += u[k] * a.y;
            acc[2] += u[k] * a.z;  acc[3] += u[k] * a.w;
            acc[4] += u[k] * bq.x; acc[5] += u[k] * bq.y;
            acc[6] += u[k] * bq.z; acc[7] += u[k] * bq.w;
        }
#pragma unroll
        for (int cc = 0; cc < 8; cc++)
            ob[(size_t)(c0 + cc) * D3_PER_EC] = acc[cc];
    }
}

// ---------------------------------------------------------------------------
// Kernel C: per (e,c,chunk) CTA, 128 threads. Thread t owns xx = t>>3 and two
// v's (v0, v0+8). D3 rows in registers as f32x2 i-pairs. Inner loop processes
// TWO b's per iteration: 6 independent values in the butterfly chain -> the
// ~130-cyc shuffle dependency is amortized over 2 b's (latency-bound fix).
// ---------------------------------------------------------------------------
__global__ void __launch_bounds__(128, 3) contract_kernel(
    const float* __restrict__ x, const float* __restrict__ U2,
    const float* __restrict__ U1, const float* __restrict__ w2,
    const float* __restrict__ w1, float* __restrict__ out) {
    int c = blockIdx.x, e = blockIdx.y;
    int t = threadIdx.x;
    int v0 = t & 7, xxi = t >> 3;
    int warp = t >> 5, lane = t & 31;

    const size_t ecoff = (size_t)(e * C_SZ + c) * D3_PER_EC;

    // d3p[h][j][q]: i-pairs of row r = j*256 + xxi*16 + v0 + 8*h  (96 regs)
    unsigned long long d3p[2][3][8];
#pragma unroll
    for (int h = 0; h < 2; h++)
#pragma unroll
        for (int j = 0; j < 3; j++) {
            const ulonglong2* p = (const ulonglong2*)(g_D3 + ecoff +
                (size_t)(j * 256 + xxi * 16 + v0 + 8 * h) * ELL);
#pragma unroll
            for (int q = 0; q < 4; q++) {
                ulonglong2 u = p[q];
                d3p[h][j][2 * q] = u.x;
                d3p[h][j][2 * q + 1] = u.y;
            }
        }

    // D2 scalars (packed into accumulator start at use)
    float d2s[2][3];
#pragma unroll
    for (int h = 0; h < 2; h++)
#pragma unroll
        for (int j = 0; j < 3; j++) {
            int r = j * 256 + xxi * 16 + v0 + 8 * h;
            float acc = 0.f;
#pragma unroll
            for (int k = 0; k < P2; k++)
                acc += U2[r * P2 + k] * w2[(e * P2 + k) * C_SZ + c];
            d2s[h][j] = acc;
        }

    float w1v = w1[e * C_SZ + c];
    float d1[3];
#pragma unroll
    for (int j = 0; j < 3; j++) d1[j] = U1[j * ELL + xxi] * w1v;

    __shared__ __align__(16) float xs[16][16];  // b-tile of x vectors
    __shared__ int border[16];
    __shared__ float wpart[4][16][3];           // per-warp partials

    // this CTA's half of the bucket
    int bb0 = g_bstart[e], bb1 = g_bstart[e + 1];
    int blen = bb1 - bb0;
    int half = (blen + NCHUNK - 1) / NCHUNK;
    int b0 = bb0 + blockIdx.z * half;
    int b1 = min(bb1, b0 + half);

    for (int tb = b0; tb < b1; tb += 16) {
        int nb = min(16, b1 - tb);
        {
            int slot = t >> 3, ii = (t & 7) * 2;
            if (slot < nb) {
                int bidx = g_order[tb + slot];
                if (ii == 0) border[slot] = bidx;
                float2 xv = *(const float2*)&x[((size_t)bidx * C_SZ + c) * ELL + ii];
                xs[slot][ii] = xv.x;
                xs[slot][ii + 1] = xv.y;
            }
        }
        __syncthreads();

        for (int s = 0; s < nb; s += 2) {
            int sB = (s + 1 < nb) ? (s + 1) : s;  // odd tail: duplicate A
            unsigned long long xpA[8], xpB[8];
            {
                const ulonglong2* xqA = (const ulonglong2*)xs[s];
                const ulonglong2* xqB = (const ulonglong2*)xs[sB];
#pragma unroll
                for (int q = 0; q < 4; q++) {
                    ulonglong2 uA = xqA[q];
                    ulonglong2 uB = xqB[q];
                    xpA[2 * q] = uA.x; xpA[2 * q + 1] = uA.y;
                    xpB[2 * q] = uB.x; xpB[2 * q + 1] = uB.y;
                }
            }
            float xxA = xs[s][xxi], xxB = xs[sB][xxi];
            float m0A = xs[s][v0] * xxA,      m1A = xs[s][v0 + 8] * xxA;
            float m0B = xs[sB][v0] * xxB,     m1B = xs[sB][v0 + 8] * xxB;

            float cA[3], cB[3];
#pragma unroll
            for (int j = 0; j < 3; j++) {
                unsigned long long a0A = pack2(d2s[0][j], 0.f);
                unsigned long long a1A = pack2(d2s[1][j], 0.f);
                unsigned long long a0B = a0A;
                unsigned long long a1B = a1A;
#pragma unroll
                for (int q = 0; q < 8; q++) {
                    a0A = fma2(d3p[0][j][q], xpA[q], a0A);
                    a1A = fma2(d3p[1][j][q], xpA[q], a1A);
                    a0B = fma2(d3p[0][j][q], xpB[q], a0B);
                    a1B = fma2(d3p[1][j][q], xpB[q], a1B);
                }
                float lo, hi, lo1, hi1;
                unpack2(lo, hi, a0A);  unpack2(lo1, hi1, a1A);
                float vA = m0A * (lo + hi) + m1A * (lo1 + hi1);
                unpack2(lo, hi, a0B);  unpack2(lo1, hi1, a1B);
                float vB = m0B * (lo + hi) + m1B * (lo1 + hi1);
                if (v0 == 0) { vA += xxA * d1[j]; vB += xxB * d1[j]; }
                cA[j] = vA; cB[j] = vB;
            }
            // interleaved butterfly: 6 independent chains hide SHFL latency
#pragma unroll
            for (int off = 16; off > 0; off >>= 1) {
                cA[0] += __shfl_xor_sync(0xffffffffu, cA[0], off);
                cB[0] += __shfl_xor_sync(0xffffffffu, cB[0], off);
                cA[1] += __shfl_xor_sync(0xffffffffu, cA[1], off);
                cB[1] += __shfl_xor_sync(0xffffffffu, cB[1], off);
                cA[2] += __shfl_xor_sync(0xffffffffu, cA[2], off);
                cB[2] += __shfl_xor_sync(0xffffffffu, cB[2], off);
            }
            if (lane == 0) {
                wpart[warp][s][0] = cA[0];
                wpart[warp][s][1] = cA[1];
                wpart[warp][s][2] = cA[2];
                if (sB != s) {
                    wpart[warp][sB][0] = cB[0];
                    wpart[warp][sB][1] = cB[1];
                    wpart[warp][sB][2] = cB[2];
                }
            }
        }
        __syncthreads();

        if (t < nb * 3) {
            int sl = t / 3, j = t - sl * 3;
            float sum = wpart[0][sl][j] + wpart[1][sl][j] +
                        wpart[2][sl][j] + wpart[3][sl][j];
            out[(size_t)border[sl] * OUT_STRIDE + c * EQ + j] = sum;
        }
        __syncthreads();
    }
}

// ---------------------------------------------------------------------------
extern "C" void kernel_launch(void* const* d_in, const int* in_sizes, int n_in,
                              void* d_out, int out_size) {
    const float* x    = (const float*)d_in[0];
    const float* y    = (const float*)d_in[1];
    const float* U3   = (const float*)d_in[2];
    const float* U2   = (const float*)d_in[3];
    const float* U1   = (const float*)d_in[4];
    const float* wmax = (const float*)d_in[5];
    const float* w2   = (const float*)d_in[6];
    const float* w1   = (const float*)d_in[7];
    float* out = (float*)d_out;

    bucket_kernel<<<1, B_SZ>>>(y);
    precomp_kernel<<<dim3(48, E_SZ), 256>>>(U3, wmax);
    contract_kernel<<<dim3(C_SZ, E_SZ, NCHUNK), 128>>>(x, U2, U1, w2, w1, out);
}

// round 9
// speedup vs baseline: 1.5414x; 1.3281x over previous
#include <cuda_runtime.h>
#include <cuda_bf16.h>
#include <cstdint>

#define B_SZ 1024
#define C_SZ 128
#define ELL 16
#define EQ 3
#define E_SZ 10
#define P3 23
#define P2 5
#define OUT_STRIDE 384
#define MROWS 48          // (w,xx) rows, m = w*16 + xx
#define KSYM 136          // symmetrized (v<=i) pairs
#define KTOT 160          // 136 + 16 + 1, padded to 160
#define KPAIR 80          // KTOT/2 bf16 pairs
#define KW 29             // 23 + 5 + 1 weight slots
#define NT 16             // b-tile
#define GSZ (MROWS * KTOT)  // 7680
#define LDA 84            // smem pair-stride (conflict-free: 84 % 32 == 20)

__device__ int g_order[B_SZ];
__device__ int g_bstart[E_SZ + 1];
__device__ __align__(16) float g_AbigT[KW * GSZ];                 // [kp][o]
__device__ __align__(16) __nv_bfloat16 g_Ghi[E_SZ * C_SZ * GSZ];  // 19.7MB
__device__ __align__(16) __nv_bfloat16 g_Glo[E_SZ * C_SZ * GSZ];

// ---------------------------------------------------------------------------
// Kernel A: bucket batch indices by element (y is exact one-hot).
// ---------------------------------------------------------------------------
__global__ void bucket_kernel(const float* __restrict__ y) {
    __shared__ int cnt[E_SZ];
    __shared__ int pfx[E_SZ + 1];
    int b = threadIdx.x;
    if (b < E_SZ) cnt[b] = 0;
    __syncthreads();
    int e = 0;
#pragma unroll
    for (int j = 1; j < E_SZ; j++)
        if (y[b * E_SZ + j] > 0.5f) e = j;
    int idx = atomicAdd(&cnt[e], 1);
    __syncthreads();
    if (b == 0) {
        int s = 0;
        for (int j = 0; j < E_SZ; j++) { pfx[j] = s; s += cnt[j]; }
        pfx[E_SZ] = s;
    }
    __syncthreads();
    g_order[pfx[e] + idx] = b;
    if (b <= E_SZ) g_bstart[b] = pfx[b];
}

// ---------------------------------------------------------------------------
// Kernel B1: build AbigT[kp][m*160+k] — element-independent coefficient matrix.
//   k <  136          : U3[m, v, i, kp] + U3[m, i, v, kp] (v<i) / diag (v==i)
//   136 <= k < 152    : U2[m, k-136, kp-23]  (slots 23..27)
//   k == 152          : U1[m]                (slot 28)
// ---------------------------------------------------------------------------
__global__ void build_abig_kernel(const float* __restrict__ U3,
                                  const float* __restrict__ U2,
                                  const float* __restrict__ U1) {
    int o = blockIdx.x * 256 + threadIdx.x;
    if (o >= GSZ) return;
    int m = o / KTOT, k = o % KTOT;
    float vals[KW];
#pragma unroll
    for (int j = 0; j < KW; j++) vals[j] = 0.f;
    if (k < KSYM) {
        int kk = k, v = 0;
        while (kk >= ELL - v) { kk -= ELL - v; v++; }
        int i = v + kk;
        const float* p1 = U3 + ((size_t)(m * ELL + v) * ELL + i) * P3;
        const float* p2 = U3 + ((size_t)(m * ELL + i) * ELL + v) * P3;
#pragma unroll
        for (int kp = 0; kp < P3; kp++)
            vals[kp] = p1[kp] + (v != i ? p2[kp] : 0.f);
    } else if (k < KSYM + ELL) {
        int v = k - KSYM;
#pragma unroll
        for (int k2 = 0; k2 < P2; k2++)
            vals[P3 + k2] = U2[(m * ELL + v) * P2 + k2];
    } else if (k == KSYM + ELL) {
        vals[P3 + P2] = U1[m];
    }
#pragma unroll
    for (int j = 0; j < KW; j++)
        g_AbigT[j * GSZ + o] = vals[j];
}

// ---------------------------------------------------------------------------
// Kernel B2: G[ec, o] = sum_kp AbigT[kp, o] * W[ec, kp]; bf16 hi/lo split.
// Grid (30, 8): bx = o-tile of 256, by = ec-tile of 160.
// ---------------------------------------------------------------------------
__global__ void __launch_bounds__(256) build_g_kernel(
    const float* __restrict__ wmax, const float* __restrict__ w2,
    const float* __restrict__ w1) {
    int o = blockIdx.x * 256 + threadIdx.x;
    int ec0 = blockIdx.y * 160;
    __shared__ __align__(16) float ws[160][32];
    for (int idx = threadIdx.x; idx < 160 * 32; idx += 256) {
        int j = idx >> 5, kp = idx & 31;
        int ec = ec0 + j, e = ec >> 7, c = ec & 127;
        float v = 0.f;
        if (kp < P3) v = wmax[(e * P3 + kp) * C_SZ + c];
        else if (kp < P3 + P2) v = w2[(e * P2 + (kp - P3)) * C_SZ + c];
        else if (kp == P3 + P2) v = w1[e * C_SZ + c];
        ws[j][kp] = v;
    }
    __syncthreads();

    float4 a4[8];
    {
        float a[32];
#pragma unroll
        for (int j = 0; j < KW; j++) a[j] = g_AbigT[j * GSZ + o];
#pragma unroll
        for (int j = KW; j < 32; j++) a[j] = 0.f;
#pragma unroll
        for (int g = 0; g < 8; g++)
            a4[g] = make_float4(a[4 * g], a[4 * g + 1], a[4 * g + 2], a[4 * g + 3]);
    }
    for (int j = 0; j < 160; j++) {
        const float4* wv = (const float4*)ws[j];
        float acc = 0.f;
#pragma unroll
        for (int g = 0; g < 8; g++) {
            float4 w4 = wv[g];
            acc += a4[g].x * w4.x + a4[g].y * w4.y + a4[g].z * w4.z + a4[g].w * w4.w;
        }
        size_t ec = (size_t)(ec0 + j);
        __nv_bfloat16 h = __float2bfloat16(acc);
        g_Ghi[ec * GSZ + o] = h;
        g_Glo[ec * GSZ + o] = __float2bfloat16(acc - __bfloat162float(h));
    }
}

// ---------------------------------------------------------------------------
// Kernel C: per (e,c) CTA, 192 threads (6 warps). G (bf16 hi/lo) in smem.
// Per 16-b tile: build z = [x_v*x_i (v<=i); x; 1] (bf16 split), then warp
// mma.sync m16n8k16 bf16: warp (mi,ni) computes Q[16mi..+15, 8ni..+7] over
// K=160 (10 k-steps x 3 mma: hh, hl, lh). Epilogue: out[w,b] = sum_xx
// xs[b][xx]*Q — fragment-local + 3-round shfl over r only.
// ---------------------------------------------------------------------------
#define MMA_BF16(A0, A1, A2, A3, B0, B1)                                    \
    asm volatile(                                                           \
        "mma.sync.aligned.m16n8k16.row.col.f32.bf16.bf16.f32 "              \
        "{%0,%1,%2,%3}, {%4,%5,%6,%7}, {%8,%9}, {%0,%1,%2,%3};"             \
        : "+f"(c0), "+f"(c1), "+f"(c2), "+f"(c3)                            \
        : "r"(A0), "r"(A1), "r"(A2), "r"(A3), "r"(B0), "r"(B1))

static __device__ __forceinline__ uint32_t bsplit(float z0, float z1, uint32_t& lo) {
    __nv_bfloat16 h0 = __float2bfloat16(z0);
    __nv_bfloat16 h1 = __float2bfloat16(z1);
    __nv_bfloat16 l0 = __float2bfloat16(z0 - __bfloat162float(h0));
    __nv_bfloat16 l1 = __float2bfloat16(z1 - __bfloat162float(h1));
    lo = ((uint32_t)__bfloat16_as_ushort(l1) << 16) | __bfloat16_as_ushort(l0);
    return ((uint32_t)__bfloat16_as_ushort(h1) << 16) | __bfloat16_as_ushort(h0);
}

__global__ void __launch_bounds__(192) contract_kernel(
    const float* __restrict__ x, float* __restrict__ out) {
    int c = blockIdx.x, e = blockIdx.y;
    int ec = e * C_SZ + c;
    int t = threadIdx.x;
    int warp = t >> 5, lane = t & 31;
    int mi = warp >> 1, ni = warp & 1;
    int r = lane >> 2, q = lane & 3;

    __shared__ uint32_t Ah[MROWS * LDA], Al[MROWS * LDA];
    __shared__ uint32_t Zh[NT * LDA], Zl[NT * LDA];
    __shared__ float xs[NT][ELL];
    __shared__ int border[NT];
    __shared__ unsigned char vlut[KSYM], ilut[KSYM];

    if (t < KSYM) {
        int kk = t, v = 0;
        while (kk >= ELL - v) { kk -= ELL - v; v++; }
        vlut[t] = (unsigned char)v;
        ilut[t] = (unsigned char)(v + kk);
    }
    {
        const uint32_t* gh = (const uint32_t*)g_Ghi + (size_t)ec * (GSZ / 2);
        const uint32_t* gl = (const uint32_t*)g_Glo + (size_t)ec * (GSZ / 2);
        for (int p = t; p < MROWS * KPAIR; p += 192) {
            int m = p / KPAIR, kk = p - m * KPAIR;
            Ah[m * LDA + kk] = gh[p];
            Al[m * LDA + kk] = gl[p];
        }
    }

    int b0 = g_bstart[e], b1 = g_bstart[e + 1];
    for (int tb = b0; tb < b1; tb += NT) {
        int nb = min(NT, b1 - tb);
        if (t < 128) {
            int slot = t >> 3, ii = (t & 7) * 2;
            if (slot < nb) {
                int bidx = g_order[tb + slot];
                if (ii == 0) border[slot] = bidx;
                float2 xv = *(const float2*)&x[((size_t)bidx * C_SZ + c) * ELL + ii];
                xs[slot][ii] = xv.x;
                xs[slot][ii + 1] = xv.y;
            } else {
                xs[slot][ii] = 0.f;
                xs[slot][ii + 1] = 0.f;
            }
        }
        __syncthreads();

        // z build: 16 b's x 80 bf16-pairs
        for (int s = t; s < NT * KPAIR; s += 192) {
            int n = s / KPAIR, kk = s - n * KPAIR;
            const float* xr = xs[n];
            float zz[2];
#pragma unroll
            for (int u = 0; u < 2; u++) {
                int k = 2 * kk + u;
                float zv;
                if (k < KSYM) zv = xr[vlut[k]] * xr[ilut[k]];
                else if (k < KSYM + ELL) zv = xr[k - KSYM];
                else zv = (k == KSYM + ELL) ? 1.f : 0.f;
                zz[u] = zv;
            }
            uint32_t lo;
            uint32_t hi = bsplit(zz[0], zz[1], lo);
            Zh[n * LDA + kk] = hi;
            Zl[n * LDA + kk] = lo;
        }
        __syncthreads();

        // GEMM: Q[m-tile, n-tile] over K=160
        float c0 = 0.f, c1 = 0.f, c2 = 0.f, c3 = 0.f;
        const uint32_t* Abh = Ah + (mi * 16 + r) * LDA + q;
        const uint32_t* Abl = Al + (mi * 16 + r) * LDA + q;
        const uint32_t* Bbh = Zh + (ni * 8 + r) * LDA + q;
        const uint32_t* Bbl = Zl + (ni * 8 + r) * LDA + q;
#pragma unroll
        for (int kt = 0; kt < 10; kt++) {
            int ko = kt * 8;
            uint32_t ah0 = Abh[ko], ah1 = Abh[ko + 8 * LDA];
            uint32_t ah2 = Abh[ko + 4], ah3 = Abh[ko + 8 * LDA + 4];
            uint32_t al0 = Abl[ko], al1 = Abl[ko + 8 * LDA];
            uint32_t al2 = Abl[ko + 4], al3 = Abl[ko + 8 * LDA + 4];
            uint32_t bh0 = Bbh[ko], bh1 = Bbh[ko + 4];
            uint32_t bl0 = Bbl[ko], bl1 = Bbl[ko + 4];
            MMA_BF16(ah0, ah1, ah2, ah3, bh0, bh1);
            MMA_BF16(ah0, ah1, ah2, ah3, bl0, bl1);
            MMA_BF16(al0, al1, al2, al3, bh0, bh1);
        }

        // epilogue: out[w,b] = sum_xx xs[b][xx] * Q[xx, b]
        int bc0 = ni * 8 + 2 * q, bc1 = bc0 + 1;
        float p0 = c0 * xs[bc0][r] + c2 * xs[bc0][r + 8];
        float p1 = c1 * xs[bc1][r] + c3 * xs[bc1][r + 8];
#pragma unroll
        for (int off = 4; off <= 16; off <<= 1) {
            p0 += __shfl_xor_sync(0xffffffffu, p0, off);
            p1 += __shfl_xor_sync(0xffffffffu, p1, off);
        }
        if (lane < 4) {
            if (bc0 < nb) out[(size_t)border[bc0] * OUT_STRIDE + c * EQ + mi] = p0;
            if (bc1 < nb) out[(size_t)border[bc1] * OUT_STRIDE + c * EQ + mi] = p1;
        }
        __syncthreads();
    }
}

// ---------------------------------------------------------------------------
extern "C" void kernel_launch(void* const* d_in, const int* in_sizes, int n_in,
                              void* d_out, int out_size) {
    const float* x    = (const float*)d_in[0];
    const float* y    = (const float*)d_in[1];
    const float* U3   = (const float*)d_in[2];
    const float* U2   = (const float*)d_in[3];
    const float* U1   = (const float*)d_in[4];
    const float* wmax = (const float*)d_in[5];
    const float* w2   = (const float*)d_in[6];
    const float* w1   = (const float*)d_in[7];
    float* out = (float*)d_out;

    bucket_kernel<<<1, B_SZ>>>(y);
    build_abig_kernel<<<30, 256>>>(U3, U2, U1);
    build_g_kernel<<<dim3(30, 8), 256>>>(wmax, w2, w1);
    contract_kernel<<<dim3(C_SZ, E_SZ), 192>>>(x, out);
}